// round 1
// baseline (speedup 1.0000x reference)
#include <cuda_runtime.h>

// Problem constants (fixed by the dataset)
#define B_TOTAL   131072
#define S_DIM     17
#define A_DIM     7
#define DPHI      128
#define DPSI      8

#define NPART     32          // blocks in the precompute kernel
#define I_PER     (DPHI / NPART)  // 4 i-values per block

// Per-block partial C matrices; reduced inside k_main. 32*128*4B = 16 KB.
__device__ float g_Cpart[NPART * 128];

// ---------------------------------------------------------------------------
// Kernel 1: block p computes partial C over i in [p*I_PER, (p+1)*I_PER).
//   M_p[j,z]  = sum_{i in chunk} w_lin[i] * K[i,j,z]
//   C_p[s,a]  = sum_{j,z} M_p[j,z] * W_phi[j,s] * W_psi[z,a]
// ---------------------------------------------------------------------------
__global__ __launch_bounds__(256)
void k_partialC(const float* __restrict__ Wphi,   // [128,17]
                const float* __restrict__ Wpsi,   // [8,7]
                const float* __restrict__ K,      // [128,128,8]
                const float* __restrict__ wlin)   // [1,128]
{
    __shared__ float Msm[DPHI * DPSI];   // 1024 floats, layout j*8+z
    __shared__ float Ctmp[256];

    const int p   = blockIdx.x;
    const int tid = threadIdx.x;        // 256 threads

    // --- M partial: each thread owns 4 consecutive (j,z) slots via float4 ---
    const float4* K4 = reinterpret_cast<const float4*>(K);
    float4 acc = make_float4(0.f, 0.f, 0.f, 0.f);
#pragma unroll
    for (int ii = 0; ii < I_PER; ii++) {
        const int i = p * I_PER + ii;
        const float w = __ldg(&wlin[i]);
        const float4 kv = K4[i * 256 + tid];   // K[i][4*tid .. 4*tid+3]
        acc.x = fmaf(w, kv.x, acc.x);
        acc.y = fmaf(w, kv.y, acc.y);
        acc.z = fmaf(w, kv.z, acc.z);
        acc.w = fmaf(w, kv.w, acc.w);
    }
    reinterpret_cast<float4*>(Msm)[tid] = acc;
    __syncthreads();

    // --- C partial: 2 threads per (s,a), each covering half the j range ---
    float c = 0.f;
    if (tid < 2 * S_DIM * A_DIM) {      // 238 active threads
        const int o    = tid >> 1;
        const int half = tid & 1;
        const int s = o / A_DIM;
        const int a = o - s * A_DIM;

        float psi[DPSI];
#pragma unroll
        for (int z = 0; z < DPSI; z++) psi[z] = __ldg(&Wpsi[z * A_DIM + a]);

        const int j0 = half * 64;
#pragma unroll 4
        for (int j = j0; j < j0 + 64; j++) {
            float inner = 0.f;
#pragma unroll
            for (int z = 0; z < DPSI; z++)
                inner = fmaf(Msm[j * DPSI + z], psi[z], inner);
            c = fmaf(__ldg(&Wphi[j * S_DIM + s]), inner, c);
        }
    }
    Ctmp[tid] = c;
    __syncthreads();

    if (tid < S_DIM * A_DIM)            // 119 outputs
        g_Cpart[p * 128 + tid] = Ctmp[2 * tid] + Ctmp[2 * tid + 1];
}

// ---------------------------------------------------------------------------
// Kernel 2: reduce partial C into smem (padded [17][8] for float4 reads),
// then out[b] = state[b,:] * C * action[b,:].  2 samples per thread.
// ---------------------------------------------------------------------------
__global__ __launch_bounds__(256)
void k_main(const float* __restrict__ state,   // [B,17]
            const float* __restrict__ action,  // [B,7]
            float* __restrict__ out)           // [B]
{
    __shared__ float Csm[S_DIM * 8];    // 136 floats, padded stride 8

    const int tid = threadIdx.x;

    if (tid < S_DIM * 8) Csm[tid] = 0.f;
    __syncthreads();
    if (tid < S_DIM * A_DIM) {
        float v = 0.f;
#pragma unroll
        for (int pp = 0; pp < NPART; pp++) v += g_Cpart[pp * 128 + tid];
        const int s = tid / A_DIM;
        const int a = tid - s * A_DIM;
        Csm[s * 8 + a] = v;
    }
    __syncthreads();

    const int b0 = blockIdx.x * 512 + tid;   // first sample
    const int b1 = b0 + 256;                 // second sample (coalesced pair)

    const float* stA = state + (size_t)b0 * S_DIM;
    const float* stB = state + (size_t)b1 * S_DIM;

    float aA0 = 0.f, aA1 = 0.f, aA2 = 0.f, aA3 = 0.f, aA4 = 0.f, aA5 = 0.f, aA6 = 0.f;
    float aB0 = 0.f, aB1 = 0.f, aB2 = 0.f, aB3 = 0.f, aB4 = 0.f, aB5 = 0.f, aB6 = 0.f;

    const float4* C4 = reinterpret_cast<const float4*>(Csm);
#pragma unroll
    for (int s = 0; s < S_DIM; s++) {
        const float4 c0 = C4[s * 2];        // C[s][0..3]
        const float4 c1 = C4[s * 2 + 1];    // C[s][4..6], pad
        const float va = stA[s];
        const float vb = stB[s];
        aA0 = fmaf(va, c0.x, aA0);  aB0 = fmaf(vb, c0.x, aB0);
        aA1 = fmaf(va, c0.y, aA1);  aB1 = fmaf(vb, c0.y, aB1);
        aA2 = fmaf(va, c0.z, aA2);  aB2 = fmaf(vb, c0.z, aB2);
        aA3 = fmaf(va, c0.w, aA3);  aB3 = fmaf(vb, c0.w, aB3);
        aA4 = fmaf(va, c1.x, aA4);  aB4 = fmaf(vb, c1.x, aB4);
        aA5 = fmaf(va, c1.y, aA5);  aB5 = fmaf(vb, c1.y, aB5);
        aA6 = fmaf(va, c1.z, aA6);  aB6 = fmaf(vb, c1.z, aB6);
    }

    const float* acA = action + (size_t)b0 * A_DIM;
    const float* acB = action + (size_t)b1 * A_DIM;

    float rA = aA0 * acA[0];
    rA = fmaf(aA1, acA[1], rA);
    rA = fmaf(aA2, acA[2], rA);
    rA = fmaf(aA3, acA[3], rA);
    rA = fmaf(aA4, acA[4], rA);
    rA = fmaf(aA5, acA[5], rA);
    rA = fmaf(aA6, acA[6], rA);

    float rB = aB0 * acB[0];
    rB = fmaf(aB1, acB[1], rB);
    rB = fmaf(aB2, acB[2], rB);
    rB = fmaf(aB3, acB[3], rB);
    rB = fmaf(aB4, acB[4], rB);
    rB = fmaf(aB5, acB[5], rB);
    rB = fmaf(aB6, acB[6], rB);

    out[b0] = rA;
    out[b1] = rB;
}

// ---------------------------------------------------------------------------
extern "C" void kernel_launch(void* const* d_in, const int* in_sizes, int n_in,
                              void* d_out, int out_size)
{
    const float* state  = (const float*)d_in[0];
    const float* action = (const float*)d_in[1];
    const float* Wphi   = (const float*)d_in[2];
    const float* Wpsi   = (const float*)d_in[3];
    const float* K      = (const float*)d_in[4];
    const float* wlin   = (const float*)d_in[5];
    float* out = (float*)d_out;

    k_partialC<<<NPART, 256>>>(Wphi, Wpsi, K, wlin);
    k_main<<<B_TOTAL / 512, 256>>>(state, action, out);
}